// round 3
// baseline (speedup 1.0000x reference)
#include <cuda_runtime.h>
#include <math.h>
#include <math_constants.h>

// Problem constants
#define HEAD_DIM 128
#define NQH      32
#define NKVH     8
#define HIDDEN   4096
#define SEQ      2048
#define KV_COLS  1024          // NKVH * HEAD_DIM
#define NCHUNK   32
#define CHUNK_ROWS 128         // 4096 / NCHUNK
#define TOT_COLS 6144          // HIDDEN + 2*KV_COLS
#define TOT4     (TOT_COLS/4)

// ---------------- scratch (no allocations allowed) ----------------
__device__ float  d_partial[NCHUNK * TOT_COLS];  // colsum partials
__device__ float  d_cq[HIDDEN];                  // colsum(Wq)
__device__ float  d_ck[KV_COLS];                 // colsum(Wk)
__device__ float  d_cv[KV_COLS];                 // colsum(Wv)
__device__ float2 d_trig[64 * SEQ];              // (cos,sin)(delta*omega_i), head-independent
__device__ float  d_g[NQH * SEQ];                // per-head relative-position score table
__device__ float  d_gblkmax[NQH * 32];           // per-head max of g over 64-delta blocks
__device__ float  d_M[NQH * HIDDEN];             // M[h,j] = sum_d cv[kvh,d]*Wo[h*128+d, j]
__device__ float  d_w[NQH * SEQ];                // w[h,q] = sum_k attn(h,q,k)*ids[k]

// ---------------- stage 1: partial column sums of Wq, Wk, Wv (float4) --------------------
__global__ void __launch_bounds__(256) colsum_stage1(const float* __restrict__ Wq,
                                                     const float* __restrict__ Wk,
                                                     const float* __restrict__ Wv) {
    int mat = blockIdx.z;
    const float* W;
    int C4, off4;
    if (mat == 0)      { W = Wq; C4 = HIDDEN / 4;  off4 = 0; }
    else if (mat == 1) { W = Wk; C4 = KV_COLS / 4; off4 = HIDDEN / 4; }
    else               { W = Wv; C4 = KV_COLS / 4; off4 = (HIDDEN + KV_COLS) / 4; }

    int col4 = blockIdx.x * 256 + threadIdx.x;
    if (col4 >= C4) return;
    const float4* p = (const float4*)W + (size_t)blockIdx.y * CHUNK_ROWS * C4 + col4;
    float4 s = make_float4(0.f, 0.f, 0.f, 0.f);
#pragma unroll 8
    for (int r = 0; r < CHUNK_ROWS; r++) {
        float4 v = p[(size_t)r * C4];
        s.x += v.x; s.y += v.y; s.z += v.z; s.w += v.w;
    }
    ((float4*)d_partial)[blockIdx.y * TOT4 + off4 + col4] = s;
}

// ---------------- stage 2: reduce partials (deterministic, float4) -----------------------
__global__ void __launch_bounds__(256) colsum_stage2() {
    int col4 = blockIdx.x * 256 + threadIdx.x;   // 0..1535
    float4 s = make_float4(0.f, 0.f, 0.f, 0.f);
#pragma unroll
    for (int c = 0; c < NCHUNK; c++) {
        float4 v = ((const float4*)d_partial)[c * TOT4 + col4];
        s.x += v.x; s.y += v.y; s.z += v.z; s.w += v.w;
    }
    if (col4 < HIDDEN / 4)                       ((float4*)d_cq)[col4] = s;
    else if (col4 < (HIDDEN + KV_COLS) / 4)      ((float4*)d_ck)[col4 - HIDDEN / 4] = s;
    else                                         ((float4*)d_cv)[col4 - (HIDDEN + KV_COLS) / 4] = s;
}

// ---------------- M[h,j] = sum_d cv[kvh*128+d] * Wo[(h*128+d)*HIDDEN + j] (float4) -------
__global__ void __launch_bounds__(256) compute_M(const float* __restrict__ Wo) {
    __shared__ float scv[HEAD_DIM];
    int h = blockIdx.y;
    int kvh = h >> 2;
    if (threadIdx.x < HEAD_DIM) scv[threadIdx.x] = d_cv[kvh * HEAD_DIM + threadIdx.x];
    __syncthreads();
    int j4 = blockIdx.x * 256 + threadIdx.x;     // 0..1023
    const float4* wp = (const float4*)Wo + (size_t)(h * HEAD_DIM) * (HIDDEN / 4) + j4;
    float4 s = make_float4(0.f, 0.f, 0.f, 0.f);
#pragma unroll 8
    for (int d = 0; d < HEAD_DIM; d++) {
        float c = scv[d];
        float4 v = wp[(size_t)d * (HIDDEN / 4)];
        s.x += c * v.x; s.y += c * v.y; s.z += c * v.z; s.w += c * v.w;
    }
    ((float4*)d_M)[h * (HIDDEN / 4) + j4] = s;
}

// ---------------- trig table: (cos,sin)(delta * omega_i), computed ONCE ------------------
__global__ void __launch_bounds__(256) compute_trig() {
    int idx = blockIdx.x * 256 + threadIdx.x;   // 0 .. 64*2048-1
    int i = idx >> 11;                          // frequency index 0..63
    int delta = idx & (SEQ - 1);                // 0..2047
    const double LN10000 = 9.210340371976184;   // ln(10000)
    double omega = exp(-((double)(2 * i) / 128.0) * LN10000);
    double th = (double)delta * omega;
    double sn, cs;
    sincos(th, &sn, &cs);
    d_trig[idx] = make_float2((float)cs, (float)sn);
}

// ---------------- g table + per-64-delta block maxima ------------------------------------
__global__ void __launch_bounds__(256) compute_g() {
    __shared__ float sA[64], sB[64];
    __shared__ float s_red[256];
    int h = blockIdx.y;
    int kvh = h >> 2;
    if (threadIdx.x < 64) {
        int i = threadIdx.x;
        float q1 = d_cq[h * HEAD_DIM + i];
        float q2 = d_cq[h * HEAD_DIM + 64 + i];
        float k1 = d_ck[kvh * HEAD_DIM + i];
        float k2 = d_ck[kvh * HEAD_DIM + 64 + i];
        sA[i] = q1 * k1 + q2 * k2;
        sB[i] = q1 * k2 - q2 * k1;
    }
    __syncthreads();
    int delta = blockIdx.x * 256 + threadIdx.x;   // 0..2047
    float acc = 0.f;
#pragma unroll 8
    for (int i = 0; i < 64; i++) {
        float2 t = d_trig[i * SEQ + delta];       // coalesced, L2-resident (1 MB table)
        acc += sA[i] * t.x + sB[i] * t.y;
    }
    d_g[h * SEQ + delta] = acc;
    s_red[threadIdx.x] = acc;
    __syncthreads();
    if (threadIdx.x < 4) {                        // 4 blocks of 64 deltas per CTA
        float m = -CUDART_INF_F;
#pragma unroll 8
        for (int i = 0; i < 64; i++) m = fmaxf(m, s_red[threadIdx.x * 64 + i]);
        d_gblkmax[h * 32 + blockIdx.x * 4 + threadIdx.x] = m;
    }
}

// ---------------- attention with block-bound pruning --------------------------------------
// scores(q,k) = alpha * u,  u = ids[k]*g[q-k],  alpha = ids[q]/sqrt(128) >= 0.
// Upper bound per 128-k block: u <= max(0, idmax128(block) * max g over delta range).
// Blocks with alpha*bound < smax-60 contribute < e^-60 each -> provably negligible.
__global__ void __launch_bounds__(256) attention(const int* __restrict__ ids) {
    __shared__ float s_g[SEQ];
    __shared__ float s_ids[SEQ];
    __shared__ float s_gblk[32];
    __shared__ float s_idmax[16];
    int h = blockIdx.y;
    int tid = threadIdx.x;
    for (int i = tid; i < SEQ; i += 256) {
        s_g[i] = d_g[h * SEQ + i];
        s_ids[i] = (float)ids[i];
    }
    if (tid < 32) s_gblk[tid] = d_gblkmax[h * 32 + tid];
    __syncthreads();
    if (tid < 16) {
        float m = 0.f;
#pragma unroll 8
        for (int i = 0; i < 128; i++) m = fmaxf(m, s_ids[tid * 128 + i]);
        s_idmax[tid] = m;
    }
    __syncthreads();

    int warp = tid >> 5, lane = tid & 31;
    int slot = blockIdx.x * 8 + warp;               // 0..127
    const float INV_SQRT_D = 0.08838834764831845f;  // 1/sqrt(128)
    const unsigned FULL = 0xffffffffu;

    for (int r = 0; r < 16; r++) {
        int q = slot + 128 * r;                     // strided: balances triangular work
        float alpha = s_ids[q] * INV_SQRT_D;
        const float* gq = s_g + q;                  // g[q-k] = gq[-k]
        float w;

        if (alpha == 0.f) {
            // all scores exactly 0 -> uniform softmax -> mean of ids[0..q]
            float ssum = 0.f;
            for (int k = lane; k <= q; k += 32) ssum += s_ids[k];
#pragma unroll
            for (int off = 16; off; off >>= 1) ssum += __shfl_xor_sync(FULL, ssum, off);
            w = ssum / (float)(q + 1);
        } else {
            int nb = (q >> 7) + 1;                  // number of 128-k blocks touching [0,q]
            // ---- per-block upper bounds (lane b handles block b) ----
            float bound = -CUDART_INF_F;
            if (lane < nb) {
                int kb = lane << 7;
                int dhi = q - kb;                   // >= 0
                int dlo = dhi - 127; if (dlo < 0) dlo = 0;
                int blo = dlo >> 6, bhi = dhi >> 6;
                float gm = s_gblk[blo];
                for (int bb = blo + 1; bb <= bhi; bb++) gm = fmaxf(gm, s_gblk[bb]);
                bound = fmaxf(0.f, s_idmax[lane] * gm);
            }
            // ---- warp-uniform argmax of bound ----
            float bb = bound; int bi = lane;
#pragma unroll
            for (int off = 16; off; off >>= 1) {
                float ob = __shfl_xor_sync(FULL, bb, off);
                int oi = __shfl_xor_sync(FULL, bi, off);
                if (ob > bb || (ob == bb && oi < bi)) { bb = ob; bi = oi; }
            }
            int bstar = bi;
            // ---- scan best block -> mhat ----
            float mh = -CUDART_INF_F;
            int kb = bstar << 7;
#pragma unroll
            for (int c = 0; c < 4; c++) {
                int k = kb + c * 32 + lane;
                float u = (k <= q) ? s_ids[k] * gq[-k] : -CUDART_INF_F;
                mh = fmaxf(mh, u);
            }
#pragma unroll
            for (int off = 16; off; off >>= 1) mh = fmaxf(mh, __shfl_xor_sync(FULL, mh, off));

            float thr = mh - 60.f / alpha;          // u-domain threshold
            unsigned mask = __ballot_sync(FULL, bound > thr) & ((nb >= 32) ? 0xffffu : ((1u << nb) - 1u)) & 0xffffu;

            // ---- true max over passing blocks ----
            float mt = mh;
            unsigned mm = mask & ~(1u << bstar);
            while (mm) {
                int b = __ffs(mm) - 1; mm &= mm - 1;
                int kb2 = b << 7;
#pragma unroll
                for (int c = 0; c < 4; c++) {
                    int k = kb2 + c * 32 + lane;
                    float u = (k <= q) ? s_ids[k] * gq[-k] : -CUDART_INF_F;
                    mt = fmaxf(mt, u);
                }
            }
#pragma unroll
            for (int off = 16; off; off >>= 1) mt = fmaxf(mt, __shfl_xor_sync(FULL, mt, off));

            // ---- accumulate over passing blocks ----
            float thr2 = mt - 60.f / alpha;
            float l = 0.f, a = 0.f;
            mm = mask;
            while (mm) {
                int b = __ffs(mm) - 1; mm &= mm - 1;
                int kb2 = b << 7;
#pragma unroll
                for (int c = 0; c < 4; c++) {
                    int k = kb2 + c * 32 + lane;
                    float idk = (k <= q) ? s_ids[k] : 0.f;
                    float u = (k <= q) ? idk * gq[-k] : -CUDART_INF_F;
                    // gate the expensive exp on any lane actually contributing
                    unsigned act = __ballot_sync(FULL, u > thr2);
                    if (act) {
                        if (u > thr2) {
                            float e = __expf(alpha * (u - mt));
                            l += e; a += e * idk;
                        }
                    }
                }
            }
#pragma unroll
            for (int off = 16; off; off >>= 1) {
                l += __shfl_xor_sync(FULL, l, off);
                a += __shfl_xor_sync(FULL, a, off);
            }
            w = a / l;
        }
        if (lane == 0) d_w[h * SEQ + q] = w;
    }
}

// ---------------- final: y[q, j] = sum_h w[h,q] * M[h,j] ----------------
__global__ void __launch_bounds__(256) final_proj(float* __restrict__ out) {
    __shared__ float s_w[32 * 64];
    int jb = blockIdx.x, qb = blockIdx.y;
    int tid = threadIdx.x;
    for (int i = tid; i < 32 * 64; i += 256) {
        int h = i >> 6, qq = i & 63;
        s_w[i] = d_w[h * SEQ + qb * 64 + qq];
    }
    __syncthreads();
    int j = jb * 256 + tid;
    float Mreg[32];
#pragma unroll
    for (int h = 0; h < 32; h++) Mreg[h] = d_M[h * HIDDEN + j];
    for (int qq = 0; qq < 64; qq++) {
        float acc = 0.f;
#pragma unroll
        for (int h = 0; h < 32; h++) acc += s_w[h * 64 + qq] * Mreg[h];
        out[(size_t)(qb * 64 + qq) * HIDDEN + j] = acc;
    }
}

// ---------------- launch ----------------
extern "C" void kernel_launch(void* const* d_in, const int* in_sizes, int n_in,
                              void* d_out, int out_size) {
    // Map inputs by element count: 2048: input_ids (first), position_ids;
    // 16777216: Wq, Wo ; 4194304: Wk, Wv
    const int* ids = nullptr;
    const float *Wq = nullptr, *Wk = nullptr, *Wv = nullptr, *Wo = nullptr;
    int seen2048 = 0, seen16m = 0, seen4m = 0;
    for (int i = 0; i < n_in; i++) {
        int sz = in_sizes[i];
        if (sz == SEQ) {
            if (seen2048++ == 0) ids = (const int*)d_in[i];
        } else if (sz == HIDDEN * HIDDEN) {
            if (seen16m++ == 0) Wq = (const float*)d_in[i];
            else                Wo = (const float*)d_in[i];
        } else if (sz == HIDDEN * KV_COLS) {
            if (seen4m++ == 0)  Wk = (const float*)d_in[i];
            else                Wv = (const float*)d_in[i];
        }
    }
    float* out = (float*)d_out;

    colsum_stage1<<<dim3(4, NCHUNK, 3), 256>>>(Wq, Wk, Wv);
    colsum_stage2<<<TOT4 / 256, 256>>>();
    compute_M<<<dim3(HIDDEN / 1024, NQH), 256>>>(Wo);
    compute_trig<<<(64 * SEQ) / 256, 256>>>();
    compute_g<<<dim3(SEQ / 256, NQH), 256>>>();
    attention<<<dim3(SEQ / 128, NQH), 256>>>(ids);
    final_proj<<<dim3(HIDDEN / 256, SEQ / 64), 256>>>(out);
}

// round 4
// speedup vs baseline: 1.1015x; 1.1015x over previous
#include <cuda_runtime.h>
#include <math.h>
#include <math_constants.h>

// Problem constants
#define HEAD_DIM 128
#define NQH      32
#define NKVH     8
#define HIDDEN   4096
#define SEQ      2048
#define KV_COLS  1024          // NKVH * HEAD_DIM
#define NCHUNK   64
#define CHUNK_ROWS 64          // 4096 / NCHUNK
#define TOT_COLS 6144          // HIDDEN + 2*KV_COLS
#define TOT4     (TOT_COLS/4)

// ---------------- scratch (no allocations allowed) ----------------
__device__ float  d_partial[NCHUNK * TOT_COLS];  // colsum partials (1.5 MB)
__device__ float  d_cq[HIDDEN];                  // colsum(Wq)
__device__ float  d_ck[KV_COLS];                 // colsum(Wk)
__device__ float  d_cv[KV_COLS];                 // colsum(Wv)
__device__ float2 d_trig[64 * SEQ];              // (cos,sin)(delta*omega_i), head-independent
__device__ float  d_g[NQH * SEQ];                // per-head relative-position score table
__device__ float  d_M[NQH * HIDDEN];             // M[h,j] = sum_d cv[kvh,d]*Wo[h*128+d, j]
__device__ float  d_w[NQH * SEQ];                // w[h,q] = sum_k attn(h,q,k)*ids[k]

// ============ K1: colsums of Wq/Wk/Wv (z=0..2) + trig table (z=3), fused ============
__global__ void __launch_bounds__(256) stage1_trig(const float* __restrict__ Wq,
                                                   const float* __restrict__ Wk,
                                                   const float* __restrict__ Wv) {
    if (blockIdx.z == 3) {
        // trig: 64*2048 = 131072 entries; 256 blocks * 256 thr * 2 each
        int base = (blockIdx.y * 4 + blockIdx.x) * 256 + threadIdx.x;
        const double LN10000 = 9.210340371976184;   // ln(10000)
#pragma unroll
        for (int rep = 0; rep < 2; rep++) {
            int idx = base + rep * 65536;
            int i = idx >> 11;                       // frequency index 0..63
            int delta = idx & (SEQ - 1);             // 0..2047
            double omega = exp(-((double)(2 * i) / 128.0) * LN10000);
            double sn, cs;
            sincos((double)delta * omega, &sn, &cs);
            d_trig[idx] = make_float2((float)cs, (float)sn);
        }
        return;
    }
    int mat = blockIdx.z;
    const float* W;
    int C4, off4;
    if (mat == 0)      { W = Wq; C4 = HIDDEN / 4;  off4 = 0; }
    else if (mat == 1) { W = Wk; C4 = KV_COLS / 4; off4 = HIDDEN / 4; }
    else               { W = Wv; C4 = KV_COLS / 4; off4 = (HIDDEN + KV_COLS) / 4; }

    int col4 = blockIdx.x * 256 + threadIdx.x;
    if (col4 >= C4) return;
    const float4* p = (const float4*)W + (size_t)blockIdx.y * CHUNK_ROWS * C4 + col4;
    float4 s = make_float4(0.f, 0.f, 0.f, 0.f);
#pragma unroll 8
    for (int r = 0; r < CHUNK_ROWS; r++) {
        float4 v = p[(size_t)r * C4];
        s.x += v.x; s.y += v.y; s.z += v.z; s.w += v.w;
    }
    ((float4*)d_partial)[blockIdx.y * TOT4 + off4 + col4] = s;
}

// ============ K2: reduce partials (deterministic, float4) ============
__global__ void __launch_bounds__(256) colsum_stage2() {
    int col4 = blockIdx.x * 256 + threadIdx.x;   // 0..1535
    float4 s = make_float4(0.f, 0.f, 0.f, 0.f);
#pragma unroll
    for (int c = 0; c < NCHUNK; c++) {
        float4 v = ((const float4*)d_partial)[c * TOT4 + col4];
        s.x += v.x; s.y += v.y; s.z += v.z; s.w += v.w;
    }
    if (col4 < HIDDEN / 4)                       ((float4*)d_cq)[col4] = s;
    else if (col4 < (HIDDEN + KV_COLS) / 4)      ((float4*)d_ck)[col4 - HIDDEN / 4] = s;
    else                                         ((float4*)d_cv)[col4 - (HIDDEN + KV_COLS) / 4] = s;
}

// ============ K3: compute_M (x<4) + compute_g (x>=4), fused ============
__global__ void __launch_bounds__(256) m_and_g(const float* __restrict__ Wo) {
    int h = blockIdx.y;
    int kvh = h >> 2;
    if (blockIdx.x < 4) {
        // ---- M[h,j] = sum_d cv[kvh*128+d] * Wo[(h*128+d)*HIDDEN + j], float4 ----
        __shared__ float scv[HEAD_DIM];
        if (threadIdx.x < HEAD_DIM) scv[threadIdx.x] = d_cv[kvh * HEAD_DIM + threadIdx.x];
        __syncthreads();
        int j4 = blockIdx.x * 256 + threadIdx.x;     // 0..1023
        const float4* wp = (const float4*)Wo + (size_t)(h * HEAD_DIM) * (HIDDEN / 4) + j4;
        float4 s = make_float4(0.f, 0.f, 0.f, 0.f);
#pragma unroll 8
        for (int d = 0; d < HEAD_DIM; d++) {
            float c = scv[d];
            float4 v = wp[(size_t)d * (HIDDEN / 4)];
            s.x += c * v.x; s.y += c * v.y; s.z += c * v.z; s.w += c * v.w;
        }
        ((float4*)d_M)[h * (HIDDEN / 4) + j4] = s;
    } else {
        // ---- g[h][delta] = sum_i A_i*cos + B_i*sin ----
        __shared__ float sA[64], sB[64];
        if (threadIdx.x < 64) {
            int i = threadIdx.x;
            float q1 = d_cq[h * HEAD_DIM + i];
            float q2 = d_cq[h * HEAD_DIM + 64 + i];
            float k1 = d_ck[kvh * HEAD_DIM + i];
            float k2 = d_ck[kvh * HEAD_DIM + 64 + i];
            sA[i] = q1 * k1 + q2 * k2;
            sB[i] = q1 * k2 - q2 * k1;
        }
        __syncthreads();
        int delta = (blockIdx.x - 4) * 256 + threadIdx.x;   // 0..2047
        float acc = 0.f;
#pragma unroll 8
        for (int i = 0; i < 64; i++) {
            float2 t = d_trig[i * SEQ + delta];             // coalesced, L2-resident
            acc += sA[i] * t.x + sB[i] * t.y;
        }
        d_g[h * SEQ + delta] = acc;
    }
}

// ============ K4: attention — branchless max pass + exact-chunk-pruned accumulate ============
// scores(q,k) = alpha * u,  u = ids[k]*g[q-k],  alpha = ids[q]/sqrt(128) >= 0.
// Pass 1 records the EXACT per-128-k-chunk max (lane-local, one ballot per chunk).
// Pass 2 visits only chunks whose max exceeds m - 60/alpha (contributions < e^-60
// otherwise -> below the reference's fp32 softmax underflow floor).
__global__ void __launch_bounds__(256) attention(const int* __restrict__ ids) {
    __shared__ float s_g[SEQ];
    __shared__ float s_ids[SEQ];
    int h = blockIdx.y;
    int tid = threadIdx.x;
    for (int i = tid; i < SEQ; i += 256) {
        s_g[i] = d_g[h * SEQ + i];
        s_ids[i] = (float)ids[i];
    }
    __syncthreads();

    int warp = tid >> 5, lane = tid & 31;
    int slot = blockIdx.x * 8 + warp;               // 0..127
    const float INV_SQRT_D = 0.08838834764831845f;  // 1/sqrt(128)
    const unsigned FULL = 0xffffffffu;

    for (int r = 0; r < 16; r++) {
        int q = slot + 128 * r;                     // strided: balances triangular work
        float alpha = s_ids[q] * INV_SQRT_D;
        const float* gq = s_g + q;                  // g[q-k] = gq[-k]
        float w;

        if (alpha == 0.f) {
            // all scores exactly 0 -> uniform softmax -> mean of ids[0..q]
            float ssum = 0.f;
            for (int k = lane; k <= q; k += 32) ssum += s_ids[k];
#pragma unroll
            for (int off = 16; off; off >>= 1) ssum += __shfl_xor_sync(FULL, ssum, off);
            w = ssum / (float)(q + 1);
        } else {
            // ---- pass 1: lane-local exact chunk maxima (16 chunks of 128 k) ----
            float cmax[16];
            float m = -CUDART_INF_F;
#pragma unroll
            for (int c = 0; c < 16; c++) {
                int kb = c << 7;
                float mc = -CUDART_INF_F;
                if (kb <= q) {
                    if (kb + 127 <= q) {            // full chunk: no predication
#pragma unroll
                        for (int j = 0; j < 4; j++) {
                            int k = kb + j * 32 + lane;
                            mc = fmaxf(mc, s_ids[k] * gq[-k]);
                        }
                    } else {                        // partial chunk
#pragma unroll
                        for (int j = 0; j < 4; j++) {
                            int k = kb + j * 32 + lane;
                            float u = (k <= q) ? s_ids[k] * gq[-k] : -CUDART_INF_F;
                            mc = fmaxf(mc, u);
                        }
                    }
                }
                cmax[c] = mc;
                m = fmaxf(m, mc);
            }
#pragma unroll
            for (int off = 16; off; off >>= 1)
                m = fmaxf(m, __shfl_xor_sync(FULL, m, off));

            float thr = m - 60.f / alpha;           // u-domain threshold

            // ---- chunk selection: any lane's exact chunk max above thr ----
            unsigned sel = 0;
#pragma unroll
            for (int c = 0; c < 16; c++) {
                unsigned b = __ballot_sync(FULL, cmax[c] > thr);
                sel |= (b ? 1u : 0u) << c;
            }

            // ---- pass 2: accumulate over selected chunks only (typically 1) ----
            float l = 0.f, a = 0.f;
            while (sel) {
                int c = __ffs(sel) - 1; sel &= sel - 1;
                int kb = c << 7;
#pragma unroll
                for (int j = 0; j < 4; j++) {
                    int k = kb + j * 32 + lane;
                    if (k <= q) {
                        float idk = s_ids[k];
                        float u = idk * gq[-k];
                        if (u > thr) {
                            float e = __expf(alpha * (u - m));
                            l += e; a += e * idk;
                        }
                    }
                }
            }
#pragma unroll
            for (int off = 16; off; off >>= 1) {
                l += __shfl_xor_sync(FULL, l, off);
                a += __shfl_xor_sync(FULL, a, off);
            }
            w = a / l;
        }
        if (lane == 0) d_w[h * SEQ + q] = w;
    }
}

// ============ K5: final y[q, j] = sum_h w[h,q] * M[h,j] ============
__global__ void __launch_bounds__(256) final_proj(float* __restrict__ out) {
    __shared__ float s_w[32 * 64];
    int jb = blockIdx.x, qb = blockIdx.y;
    int tid = threadIdx.x;
    for (int i = tid; i < 32 * 64; i += 256) {
        int h = i >> 6, qq = i & 63;
        s_w[i] = d_w[h * SEQ + qb * 64 + qq];
    }
    __syncthreads();
    int j = jb * 256 + tid;
    float Mreg[32];
#pragma unroll
    for (int h = 0; h < 32; h++) Mreg[h] = d_M[h * HIDDEN + j];
    for (int qq = 0; qq < 64; qq++) {
        float acc = 0.f;
#pragma unroll
        for (int h = 0; h < 32; h++) acc += s_w[h * 64 + qq] * Mreg[h];
        out[(size_t)(qb * 64 + qq) * HIDDEN + j] = acc;
    }
}

// ---------------- launch ----------------
extern "C" void kernel_launch(void* const* d_in, const int* in_sizes, int n_in,
                              void* d_out, int out_size) {
    // Map inputs by element count: 2048: input_ids (first), position_ids;
    // 16777216: Wq, Wo ; 4194304: Wk, Wv
    const int* ids = nullptr;
    const float *Wq = nullptr, *Wk = nullptr, *Wv = nullptr, *Wo = nullptr;
    int seen2048 = 0, seen16m = 0, seen4m = 0;
    for (int i = 0; i < n_in; i++) {
        int sz = in_sizes[i];
        if (sz == SEQ) {
            if (seen2048++ == 0) ids = (const int*)d_in[i];
        } else if (sz == HIDDEN * HIDDEN) {
            if (seen16m++ == 0) Wq = (const float*)d_in[i];
            else                Wo = (const float*)d_in[i];
        } else if (sz == HIDDEN * KV_COLS) {
            if (seen4m++ == 0)  Wk = (const float*)d_in[i];
            else                Wv = (const float*)d_in[i];
        }
    }
    float* out = (float*)d_out;

    stage1_trig<<<dim3(4, NCHUNK, 4), 256>>>(Wq, Wk, Wv);
    colsum_stage2<<<TOT4 / 256, 256>>>();
    m_and_g<<<dim3(12, NQH), 256>>>(Wo);
    attention<<<dim3(SEQ / 128, NQH), 256>>>(ids);
    final_proj<<<dim3(HIDDEN / 256, SEQ / 64), 256>>>(out);
}